// round 3
// baseline (speedup 1.0000x reference)
#include <cuda_runtime.h>
#include <cstdint>

namespace {
constexpr int L2C  = 65536;
constexpr int NC   = 2 * L2C;     // 131072
constexpr int FINC = 8;
constexpr int FOUTC= 8;
constexpr int KC   = 13;
constexpr int IK   = FINC * KC;   // 104
constexpr int EPB  = 32;          // edges per block
constexpr int TPB  = 256;         // EPB * FOUTC
constexpr int PADW = 108;         // row pad (floats): 12*o banks -> conflict-free
constexpr int WPE  = IK * FOUTC / 32;  // bitmask words per edge = 832/32 = 26
constexpr int MBS  = 28;          // mb row stride (pad)
}

// Scratch: x transposed to (N, FIN) so one gather = one 32B sector.
__device__ __align__(16) float g_xt[(size_t)NC * FINC];
// 1 => masks are 1-byte elements; 0 => masks are 4-byte words
__device__ int g_mask_is_byte;

__global__ void detect_kernel(const uint32_t* __restrict__ M) {
    int bad = 0;
    for (int i = threadIdx.x; i < 1024; i += 32) {
        uint32_t w = M[i];
        if (!(w == 0u || w == 1u || w == 0x3f800000u)) bad = 1;
    }
    bad = __any_sync(0xffffffffu, bad);
    if (threadIdx.x == 0) g_mask_is_byte = bad;
}

__global__ __launch_bounds__(TPB) void transpose_kernel(const float* __restrict__ x) {
    int j = blockIdx.x * blockDim.x + threadIdx.x;
    if (j >= NC) return;
    float4 a, b;
    a.x = x[0 * NC + j]; a.y = x[1 * NC + j]; a.z = x[2 * NC + j]; a.w = x[3 * NC + j];
    b.x = x[4 * NC + j]; b.y = x[5 * NC + j]; b.z = x[6 * NC + j]; b.w = x[7 * NC + j];
    float4* dst = reinterpret_cast<float4*>(g_xt) + (size_t)j * 2;
    dst[0] = a;
    dst[1] = b;
}

__global__ __launch_bounds__(TPB) void edge_kernel(
    const float* __restrict__ Wh, const float* __restrict__ Wv,
    const float* __restrict__ bh, const float* __restrict__ bv,
    const uint8_t* __restrict__ Mh, const uint8_t* __restrict__ Mv,
    const int* __restrict__ Kh, const int* __restrict__ Kv,
    const int* __restrict__ ELh, const int* __restrict__ ELv,
    float* __restrict__ out)
{
    const bool vert = (blockIdx.y != 0);
    const float*   W    = vert ? Wv  : Wh;
    const float*   bias = vert ? bv  : bh;
    const uint8_t* M    = vert ? Mv  : Mh;
    const int*     KER  = vert ? Kv  : Kh;
    const int*     EL   = vert ? ELv : ELh;

    __shared__ float    Ws[FOUTC * PADW];
    __shared__ float    xs[EPB * PADW];
    __shared__ uint32_t mb[EPB * MBS];     // per-edge 26 bitmask words (bit = mask word nonzero)
    __shared__ int      kers[EPB * KC];
    __shared__ float    bs[FOUTC];

    const int tid  = threadIdx.x;
    const int lane = tid & 31;
    const int warp = tid >> 5;
    const int e0   = blockIdx.x * EPB;

    // ---- stage small constants ----
    for (int t = tid; t < FOUTC * IK; t += TPB)
        Ws[(t / IK) * PADW + (t % IK)] = W[t];
    if (tid < FOUTC) bs[tid] = bias[tid];
    for (int t = tid; t < EPB * KC; t += TPB)
        kers[t] = KER[e0 * KC + t];

    const int mask_is_byte = g_mask_is_byte;

    if (!mask_is_byte) {
        // ---- coalesced mask stream + ballot bit-pack ----
        // Block mask region: 32 edges * 832 words = 26624 words = 832 bitmask groups.
        // Warp w packs groups [w*104, (w+1)*104); group t covers words 32t..32t+31.
        const uint32_t* Mw = reinterpret_cast<const uint32_t*>(M) +
                             (size_t)e0 * (FOUTC * IK);
        const int tbase = warp * 104;
        #pragma unroll 4
        for (int n = 0; n < 104; n++) {
            int t = tbase + n;
            uint32_t w32 = Mw[(size_t)t * 32 + lane];          // 128B coalesced per warp
            uint32_t bmask = __ballot_sync(0xffffffffu, w32 != 0u);
            if (lane == 0) {
                int el  = t / WPE;           // t / 26
                int idx = t - el * WPE;      // t % 26
                mb[el * MBS + idx] = bmask;
            }
        }
    }

    __syncthreads();

    const int el = tid >> 3;   // local edge 0..31
    const int o  = tid & 7;    // output feature 0..7

    // ---- cooperative x gather: thread (el,o) supplies feature i=o for its edge ----
    #pragma unroll
    for (int k = 0; k < KC; k++) {
        int j = kers[el * KC + k];
        xs[el * PADW + o * KC + k] = g_xt[(size_t)j * FINC + o];
    }
    __syncthreads();

    float acc = bs[o];
    const float4* Wr = reinterpret_cast<const float4*>(Ws + o * PADW);
    const float4* xr = reinterpret_cast<const float4*>(xs + el * PADW);

    if (!mask_is_byte) {
        // ---- extract this thread's 104 mask bits (bit positions [o*104, o*104+104)) ----
        const int bitbase = o * IK;            // o*104
        const int w0 = bitbase >> 5;
        const int sh = bitbase & 31;           // in {0,8,16,24}
        const uint32_t* mrow = mb + el * MBS + w0;
        uint32_t m0 = mrow[0], m1 = mrow[1], m2 = mrow[2], m3 = mrow[3];
        uint32_t a0 = __funnelshift_r(m0, m1, sh);
        uint32_t a1 = __funnelshift_r(m1, m2, sh);
        uint32_t a2 = __funnelshift_r(m2, m3, sh);
        uint32_t a3 = m3 >> sh;                // only low 8 bits needed
        uint32_t a[4] = {a0, a1, a2, a3};

        #pragma unroll
        for (int q = 0; q < IK / 4; q++) {     // 26
            uint32_t nib = (a[q >> 3] >> ((q & 7) * 4)) & 0xFu;
            float4 wv = Wr[q];
            float4 xv = xr[q];
            if (nib & 1u) acc = fmaf(wv.x, xv.x, acc);
            if (nib & 2u) acc = fmaf(wv.y, xv.y, acc);
            if (nib & 4u) acc = fmaf(wv.z, xv.z, acc);
            if (nib & 8u) acc = fmaf(wv.w, xv.w, acc);
        }
    } else {
        // ---- fallback: masks are 1-byte elements (direct per-thread read) ----
        const uint2* mp = reinterpret_cast<const uint2*>(
            M + (size_t)(e0 + el) * (FOUTC * IK) + (size_t)o * IK);
        #pragma unroll
        for (int q = 0; q < IK / 4; q++) {
            uint2 mw = mp[q >> 1];
            uint32_t m = (q & 1) ? mw.y : mw.x;
            float4 wv = Wr[q];
            float4 xv = xr[q];
            if (m & 0x000000ffu) acc = fmaf(wv.x, xv.x, acc);
            if (m & 0x0000ff00u) acc = fmaf(wv.y, xv.y, acc);
            if (m & 0x00ff0000u) acc = fmaf(wv.z, xv.z, acc);
            if (m & 0xff000000u) acc = fmaf(wv.w, xv.w, acc);
        }
    }

    const float SCALE = (float)((2.0 + 2.0 * 2.718281828459045235) /
                                (2.718281828459045235 - 1.0));
    float s   = 1.0f / (1.0f + __expf(-acc));
    float res = (s - 0.5f) * SCALE;

    int col = EL[e0 + el];
    out[(size_t)o * NC + col] = res;
}

extern "C" void kernel_launch(void* const* d_in, const int* in_sizes, int n_in,
                              void* d_out, int out_size) {
    const float*   x   = (const float*)  d_in[0];
    const float*   Wh  = (const float*)  d_in[1];
    const float*   Wv  = (const float*)  d_in[2];
    const float*   bh  = (const float*)  d_in[3];
    const float*   bv  = (const float*)  d_in[4];
    const uint8_t* Mh  = (const uint8_t*)d_in[5];
    const uint8_t* Mv  = (const uint8_t*)d_in[6];
    const int*     Kh  = (const int*)    d_in[7];
    const int*     Kv  = (const int*)    d_in[8];
    const int*     ELh = (const int*)    d_in[9];
    const int*     ELv = (const int*)    d_in[10];
    float* out = (float*)d_out;

    detect_kernel<<<1, 32>>>((const uint32_t*)Mh);
    transpose_kernel<<<NC / TPB, TPB>>>(x);

    dim3 grid(L2C / EPB, 2);   // y=0 horizontal branch, y=1 vertical
    edge_kernel<<<grid, TPB>>>(Wh, Wv, bh, bv, Mh, Mv, Kh, Kv, ELh, ELv, out);
}

// round 4
// speedup vs baseline: 1.2306x; 1.2306x over previous
#include <cuda_runtime.h>
#include <cstdint>

namespace {
constexpr int L2C  = 65536;
constexpr int NC   = 2 * L2C;       // 131072
constexpr int FINC = 8;
constexpr int FOUTC= 8;
constexpr int KC   = 13;
constexpr int IK   = FINC * KC;     // 104
constexpr int EPB  = 32;            // edges per block
constexpr int TPB  = 256;
constexpr int CHE  = 4;             // edges per chunk
constexpr int NCH  = EPB / CHE;     // 8 chunks
constexpr int MROW = 24;            // bytes per lane' mask row (3*lane mod 16 distinct -> conflict-free)
constexpr int XROW = 20;            // floats per (edge,i) x row (5*i mod 8 distinct -> conflict-free)
constexpr int WPEDGE = IK * FOUTC;  // 832 mask words per edge
constexpr int CHW  = CHE * WPEDGE;  // 3328 words per chunk
constexpr int STIT = CHW / TPB;     // 13 staging iterations (exact)
}

// x transposed to (N, FIN): one gathered column = one 32B sector.
__device__ __align__(16) float g_xt[(size_t)NC * FINC];
// 1 => masks are 1-byte elements; 0 => 4-byte words ({0,1} int or {0,1.0f} float)
__device__ int g_mask_is_byte;

__global__ __launch_bounds__(TPB) void prep_kernel(const float* __restrict__ x,
                                                   const uint32_t* __restrict__ M) {
    // block 0, warp 0: mask dtype detection (overlapped with transpose work)
    if (blockIdx.x == 0 && threadIdx.x < 32) {
        int bad = 0;
        for (int i = threadIdx.x; i < 128; i += 32) {
            uint32_t w = M[i];
            if (!(w == 0u || w == 1u || w == 0x3f800000u)) bad = 1;
        }
        bad = __any_sync(0xffffffffu, bad);
        if (threadIdx.x == 0) g_mask_is_byte = bad;
    }
    int j = blockIdx.x * blockDim.x + threadIdx.x;
    if (j >= NC) return;
    float4 a, b;
    a.x = x[0 * NC + j]; a.y = x[1 * NC + j]; a.z = x[2 * NC + j]; a.w = x[3 * NC + j];
    b.x = x[4 * NC + j]; b.y = x[5 * NC + j]; b.z = x[6 * NC + j]; b.w = x[7 * NC + j];
    float4* dst = reinterpret_cast<float4*>(g_xt) + (size_t)j * 2;
    dst[0] = a;
    dst[1] = b;
}

__global__ __launch_bounds__(TPB) void edge_kernel(
    const float* __restrict__ Wh, const float* __restrict__ Wv,
    const float* __restrict__ bh, const float* __restrict__ bv,
    const uint8_t* __restrict__ Mh, const uint8_t* __restrict__ Mv,
    const int* __restrict__ Kh, const int* __restrict__ Kv,
    const int* __restrict__ ELh, const int* __restrict__ ELv,
    float* __restrict__ out)
{
    const bool vert = (blockIdx.y != 0);
    const float*   W    = vert ? Wv  : Wh;
    const float*   bias = vert ? bv  : bh;
    const uint8_t* M    = vert ? Mv  : Mh;
    const int*     KER  = vert ? Kv  : Kh;
    const int*     EL   = vert ? ELv : ELh;

    __shared__ __align__(16) uint8_t mbuf[2][CHE * 64 * MROW];   // 2 x 6144 B
    __shared__ __align__(16) float   xs[EPB * FINC * XROW];      // 20480 B
    __shared__ int   kers[EPB * KC];
    __shared__ float bsh[FOUTC];
    __shared__ int   els[EPB];

    const int tid = threadIdx.x;
    const int e0  = blockIdx.x * EPB;

    // ---- stage small tables ----
    for (int t = tid; t < EPB * KC; t += TPB) kers[t] = KER[e0 * KC + t];
    if (tid < EPB)   els[tid] = EL[e0 + tid];
    if (tid < FOUTC) bsh[tid] = bias[tid];
    __syncthreads();

    // ---- x gather (mapping: el=tid>>3, feat=tid&7): 8 consecutive floats per
    //      column -> 4 x 32B sectors per warp-LDG; write into padded XROW layout ----
    {
        int gel = tid >> 3, gi = tid & 7;
        #pragma unroll
        for (int k = 0; k < KC; k++) {
            int j = kers[gel * KC + k];
            xs[(gel * FINC + gi) * XROW + k] = g_xt[(size_t)j * FINC + gi];
        }
    }

    // ---- compute-role decomposition: tid = (cel<2b> half<1b> oh<2b> i<3b>) ----
    const int cel  = tid >> 6;          // chunk-local edge 0..3
    const int lane = tid & 31;
    const int half = (tid >> 5) & 1;    // o-half
    const int oh   = lane >> 3;
    const int ii   = lane & 7;          // input feature
    const int o    = half * 4 + oh;     // output feature

    // W for (o, ii): 13 registers, loaded once per block (L1/L2-resident)
    float wreg[KC];
    #pragma unroll
    for (int k = 0; k < KC; k++) wreg[k] = W[(o * FINC + ii) * KC + k];

    const int isbyte = g_mask_is_byte;
    const uint32_t* Mw = reinterpret_cast<const uint32_t*>(M) + (size_t)e0 * WPEDGE;
    const uint8_t*  M8 = M + (size_t)e0 * WPEDGE;

    // ---- prefetch chunk 0 mask words (coalesced, fully pipelined: 13 independent LDGs) ----
    uint32_t pw[STIT];
    #pragma unroll
    for (int it = 0; it < STIT; it++) {
        int u = it * TPB + tid;
        pw[it] = isbyte ? (uint32_t)M8[u] : Mw[u];
    }

    const float SCALE = (float)((2.0 + 2.0 * 2.718281828459045235) /
                                (2.718281828459045235 - 1.0));

    for (int c = 0; c < NCH; c++) {
        const int bsel = c & 1;
        // ---- store predicates of chunk c (1 byte each, 24B-stride rows) ----
        #pragma unroll
        for (int it = 0; it < STIT; it++) {
            int u  = it * TPB + tid;
            int el = u / WPEDGE;
            int w  = u - el * WPEDGE;
            int lp = w / KC;            // lane' = 8*o + i  (0..63)
            int j  = w - lp * KC;
            mbuf[bsel][(el * 64 + lp) * MROW + j] = (pw[it] != 0u) ? 1u : 0u;
        }
        // ---- prefetch chunk c+1 ----
        if (c + 1 < NCH) {
            size_t base = (size_t)(c + 1) * CHW;
            #pragma unroll
            for (int it = 0; it < STIT; it++) {
                int u = it * TPB + tid;
                pw[it] = isbyte ? (uint32_t)M8[base + u] : Mw[base + u];
            }
        }
        __syncthreads();   // chunk c staged; buffer bsel safe vs chunk c-2 consumers

        // ---- compute chunk c: thread (cel, o, ii) does 13 k-products ----
        const int eg = c * CHE + cel;   // block-local edge
        const uint8_t* mrow = &mbuf[bsel][(cel * 64 + half * 32 + lane) * MROW];
        uint64_t m0 = *reinterpret_cast<const uint64_t*>(mrow);       // bytes k=0..7
        uint64_t m1 = *reinterpret_cast<const uint64_t*>(mrow + 8);   // bytes k=8..12

        const float* xr = &xs[(eg * FINC + ii) * XROW];
        float4 xa = *reinterpret_cast<const float4*>(xr);
        float4 xb = *reinterpret_cast<const float4*>(xr + 4);
        float4 xc = *reinterpret_cast<const float4*>(xr + 8);
        float  xd = xr[12];

        float acc = 0.0f;
        if ((m0 >>  0) & 0xffu) acc = fmaf(wreg[0],  xa.x, acc);
        if ((m0 >>  8) & 0xffu) acc = fmaf(wreg[1],  xa.y, acc);
        if ((m0 >> 16) & 0xffu) acc = fmaf(wreg[2],  xa.z, acc);
        if ((m0 >> 24) & 0xffu) acc = fmaf(wreg[3],  xa.w, acc);
        if ((m0 >> 32) & 0xffu) acc = fmaf(wreg[4],  xb.x, acc);
        if ((m0 >> 40) & 0xffu) acc = fmaf(wreg[5],  xb.y, acc);
        if ((m0 >> 48) & 0xffu) acc = fmaf(wreg[6],  xb.z, acc);
        if ((m0 >> 56) & 0xffu) acc = fmaf(wreg[7],  xb.w, acc);
        if ((m1 >>  0) & 0xffu) acc = fmaf(wreg[8],  xc.x, acc);
        if ((m1 >>  8) & 0xffu) acc = fmaf(wreg[9],  xc.y, acc);
        if ((m1 >> 16) & 0xffu) acc = fmaf(wreg[10], xc.z, acc);
        if ((m1 >> 24) & 0xffu) acc = fmaf(wreg[11], xc.w, acc);
        if ((m1 >> 32) & 0xffu) acc = fmaf(wreg[12], xd,   acc);

        // reduce over input features (lane bits 0..2)
        acc += __shfl_xor_sync(0xffffffffu, acc, 1);
        acc += __shfl_xor_sync(0xffffffffu, acc, 2);
        acc += __shfl_xor_sync(0xffffffffu, acc, 4);

        if (ii == 0) {
            float z = acc + bsh[o];
            float s = 1.0f / (1.0f + __expf(-z));
            out[(size_t)o * NC + els[eg]] = (s - 0.5f) * SCALE;
        }
        // single barrier per iteration is sufficient with 2 buffers (see analysis)
    }
}

extern "C" void kernel_launch(void* const* d_in, const int* in_sizes, int n_in,
                              void* d_out, int out_size) {
    const float*   x   = (const float*)  d_in[0];
    const float*   Wh  = (const float*)  d_in[1];
    const float*   Wv  = (const float*)  d_in[2];
    const float*   bh  = (const float*)  d_in[3];
    const float*   bv  = (const float*)  d_in[4];
    const uint8_t* Mh  = (const uint8_t*)d_in[5];
    const uint8_t* Mv  = (const uint8_t*)d_in[6];
    const int*     Kh  = (const int*)    d_in[7];
    const int*     Kv  = (const int*)    d_in[8];
    const int*     ELh = (const int*)    d_in[9];
    const int*     ELv = (const int*)    d_in[10];
    float* out = (float*)d_out;

    prep_kernel<<<NC / TPB, TPB>>>(x, (const uint32_t*)Mh);

    dim3 grid(L2C / EPB, 2);   // y=0 horizontal branch, y=1 vertical
    edge_kernel<<<grid, TPB>>>(Wh, Wv, bh, bv, Mh, Mv, Kh, Kv, ELh, ELv, out);
}